// round 1
// baseline (speedup 1.0000x reference)
#include <cuda_runtime.h>
#include <stdint.h>

#define NTOT  (8*32*32*9)   // 73728
#define KSEL  512
#define HF_   32
#define WF_   32
#define CCH   1024
#define FEAT  256
#define OUTC  84
#define SS_   14
#define NSAMP 196
#define DET_THRC 0.7f
#define NMS_IOUC 0.7f

// ---------------- device scratch (static globals; no runtime alloc) ----------
__device__ uint64_t g_cand[NTOT];
__device__ int      g_cand_count;
__device__ int      g_sel_idx[KSEL];
__device__ int      g_valid[KSEL];
__device__ int      g_assign[KSEL];
__device__ float    g_rois[KSEL*4];
__device__ float    g_shifted[KSEL*4];
__device__ unsigned g_sup[KSEL*16];
__device__ unsigned g_supany[16];
__device__ int      g_keep[KSEL];
__device__ float    g_pooled[KSEL*CCH];
__device__ float    g_hdd[KSEL*FEAT];

// ---------------- init ----------------
__global__ void k_init() {
    if (threadIdx.x == 0) g_cand_count = 0;
    if (threadIdx.x < 16) g_supany[threadIdx.x] = 0u;
}

// ---------------- filter: score > 0.7 -> 64-bit sortable key ----------------
__global__ void k_filter(const float* __restrict__ pred) {
    int i = blockIdx.x * blockDim.x + threadIdx.x;
    if (i < NTOT) {
        float s = pred[i];
        if (s > DET_THRC) {
            unsigned u = __float_as_uint(s); // s > 0 -> monotone as unsigned
            int pos = atomicAdd(&g_cand_count, 1);
            g_cand[pos] = ((uint64_t)u << 32) | (unsigned)(0xFFFFFFFFu - (unsigned)i);
        }
    }
}

// ---------------- single-block radix-select + bitonic sort top-512 ----------
__global__ void __launch_bounds__(1024) k_select(const float* __restrict__ rois,
                                                 const float* __restrict__ anchors,
                                                 const int*   __restrict__ assign) {
    __shared__ unsigned sh_hist[256];
    __shared__ unsigned sh_prefix;
    __shared__ int      sh_target;
    __shared__ int      sh_cnt;
    __shared__ uint64_t sh_keys[1024];
    int tid = threadIdx.x;
    int M = g_cand_count; if (M > NTOT) M = NTOT;

    unsigned T = 1u; // collect everything valid if M <= KSEL
    if (M > KSEL) {
        if (tid == 0) { sh_prefix = 0u; sh_target = KSEL; }
        __syncthreads();
        for (int shift = 24; shift >= 0; shift -= 8) {
            if (tid < 256) sh_hist[tid] = 0u;
            __syncthreads();
            unsigned pfx = sh_prefix;
            for (int j = tid; j < M; j += 1024) {
                unsigned u = (unsigned)(g_cand[j] >> 32);
                bool match = (shift == 24) || ((u >> (shift + 8)) == (pfx >> (shift + 8)));
                if (match) atomicAdd(&sh_hist[(u >> shift) & 255], 1u);
            }
            __syncthreads();
            if (tid == 0) {
                int tgt = sh_target;
                int cum = 0; int chosen = 0;
                for (int d = 255; d >= 0; d--) {
                    cum += (int)sh_hist[d];
                    if (cum >= tgt) { chosen = d; sh_target = tgt - (cum - (int)sh_hist[d]); break; }
                }
                sh_prefix = pfx | ((unsigned)chosen << shift);
            }
            __syncthreads();
        }
        T = sh_prefix;
    }

    // collect keys with score-bits >= T
    if (tid == 0) sh_cnt = 0;
    __syncthreads();
    for (int j = tid; j < M; j += 1024) {
        uint64_t k = g_cand[j];
        unsigned u = (unsigned)(k >> 32);
        if (u >= T) {
            int p = atomicAdd(&sh_cnt, 1);
            if (p < 1024) sh_keys[p] = k;
        }
    }
    __syncthreads();
    int cnt = sh_cnt; if (cnt > 1024) cnt = 1024;
    if (tid >= cnt) sh_keys[tid] = 0ull;
    __syncthreads();

    // bitonic sort 1024 keys, descending (ties impossible: key embeds ~idx)
    for (int size = 2; size <= 1024; size <<= 1) {
        for (int stride = size >> 1; stride > 0; stride >>= 1) {
            int i = tid;
            int j = i ^ stride;
            if (j > i) {
                uint64_t a = sh_keys[i], b = sh_keys[j];
                bool descBlk = ((i & size) == 0);
                if (descBlk ? (a < b) : (a > b)) { sh_keys[i] = b; sh_keys[j] = a; }
            }
            __syncthreads();
        }
    }

    if (tid < KSEL) {
        uint64_t k = sh_keys[tid];
        unsigned u = (unsigned)(k >> 32);
        int idx = 0, v = 0;
        if (u != 0u) { idx = (int)(0xFFFFFFFFu - (unsigned)(k & 0xFFFFFFFFu)); v = 1; }
        g_sel_idx[tid] = idx;
        g_valid[tid]   = v;
        int a = assign[idx];
        g_assign[tid]  = a;
        float fa = (float)a * 1024.0f;
        #pragma unroll
        for (int c = 0; c < 4; c++) g_rois[tid*4 + c] = rois[idx*4 + c];
        float cy = anchors[idx*4+0], cx = anchors[idx*4+1];
        float hh = anchors[idx*4+2], ww = anchors[idx*4+3];
        g_shifted[tid*4+0] = cy - hh*0.5f + fa;
        g_shifted[tid*4+1] = cx - ww*0.5f + fa;
        g_shifted[tid*4+2] = cy + hh*0.5f + fa;
        g_shifted[tid*4+3] = cx + ww*0.5f + fa;
    }
}

// ---------------- NMS suppression bitmask: thread = (box i, 32-j word) ------
__global__ void k_sup() {
    int gid = blockIdx.x * blockDim.x + threadIdx.x;
    if (gid >= KSEL * 16) return;
    int i = gid >> 4;
    int w = gid & 15;
    float y1 = g_shifted[i*4+0], x1 = g_shifted[i*4+1];
    float y2 = g_shifted[i*4+2], x2 = g_shifted[i*4+3];
    float ai = (y2 - y1) * (x2 - x1);
    unsigned bits = 0u;
    #pragma unroll 4
    for (int b = 0; b < 32; b++) {
        int j = w*32 + b;
        if (j > i) {
            float by1 = g_shifted[j*4+0], bx1 = g_shifted[j*4+1];
            float by2 = g_shifted[j*4+2], bx2 = g_shifted[j*4+3];
            float yA = fmaxf(y1, by1), xA = fmaxf(x1, bx1);
            float yB = fminf(y2, by2), xB = fminf(x2, bx2);
            float inter = fmaxf(yB - yA, 0.0f) * fmaxf(xB - xA, 0.0f);
            float aj = (by2 - by1) * (bx2 - bx1);
            float iou = inter / (ai + aj - inter + 1e-8f);
            if (iou > NMS_IOUC) bits |= (1u << b);
        }
    }
    g_sup[i*16 + w] = bits;
    if (bits) atomicOr(&g_supany[i >> 5], 1u << (i & 31));
}

// ---------------- sequential greedy resolve, 1 warp, skip empty rows --------
__global__ void k_resolve() {
    int lane = threadIdx.x;
    unsigned word = 0u;
    if (lane < 16) {
        #pragma unroll
        for (int b = 0; b < 32; b++)
            if (g_valid[lane*32 + b]) word |= (1u << b);
    }
    for (int w = 0; w < 16; w++) {
        unsigned anyw = g_supany[w];   // uniform across lanes
        if (!anyw) continue;
        for (int b = 0; b < 32; b++) {
            if (!((anyw >> b) & 1u)) continue;
            int i = w*32 + b;
            unsigned wi = __shfl_sync(0xffffffffu, word, w);
            if ((wi >> b) & 1u) {
                if (lane < 16) word &= ~g_sup[i*16 + lane];
            }
        }
    }
    if (lane < 16) {
        #pragma unroll
        for (int b = 0; b < 32; b++)
            g_keep[lane*32 + b] = (int)((word >> b) & 1u);
    }
}

// ---------------- ROI align via per-pixel weight map (1 block / roi) --------
__global__ void __launch_bounds__(256) k_roialign(const float* __restrict__ feats) {
    __shared__ float wmap[1024];
    __shared__ int   plist[800];
    __shared__ float wlist[800];
    __shared__ int   cnt;
    int k   = blockIdx.x;
    int tid = threadIdx.x;
    for (int i = tid; i < 1024; i += 256) wmap[i] = 0.0f;
    if (tid == 0) cnt = 0;
    __syncthreads();

    const float sc = 32.0f / 1024.0f;
    float ry1 = g_rois[k*4+0] * sc, rx1 = g_rois[k*4+1] * sc;
    float ry2 = g_rois[k*4+2] * sc, rx2 = g_rois[k*4+3] * sc;

    if (tid < NSAMP) {
        int sy = tid / SS_, sx = tid % SS_;
        float fy = ((float)sy + 0.5f) / (float)SS_;
        float fx = ((float)sx + 0.5f) / (float)SS_;
        float yy = ry1 + fy * (ry2 - ry1) - 0.5f;
        float xx = rx1 + fx * (rx2 - rx1) - 0.5f;
        float yc = fminf(fmaxf(yy, 0.0f), 31.0f);
        float xc = fminf(fmaxf(xx, 0.0f), 31.0f);
        float y0 = floorf(yc), x0 = floorf(xc);
        float wy = yc - y0,  wx = xc - x0;
        int y0i = (int)y0, x0i = (int)x0;
        int y1i = min(y0i + 1, 31), x1i = min(x0i + 1, 31);
        atomicAdd(&wmap[y0i*32 + x0i], (1.0f - wy) * (1.0f - wx));
        atomicAdd(&wmap[y0i*32 + x1i], (1.0f - wy) * wx);
        atomicAdd(&wmap[y1i*32 + x0i], wy * (1.0f - wx));
        atomicAdd(&wmap[y1i*32 + x1i], wy * wx);
    }
    __syncthreads();

    for (int p = tid; p < 1024; p += 256) {
        float w = wmap[p];
        if (w != 0.0f) {
            int pos = atomicAdd(&cnt, 1);
            plist[pos] = p; wlist[pos] = w;
        }
    }
    __syncthreads();

    int n = cnt;
    const float* fb = feats + (size_t)g_assign[k] * (HF_ * WF_ * CCH);
    float a0 = 0.f, a1 = 0.f, a2 = 0.f, a3 = 0.f;
    for (int e = 0; e < n; e++) {
        int   p = plist[e];
        float w = wlist[e];
        const float* row = fb + (size_t)p * CCH + tid;
        a0 += w * row[0];
        a1 += w * row[256];
        a2 += w * row[512];
        a3 += w * row[768];
    }
    const float inv = 1.0f / 196.0f;
    float* po = g_pooled + (size_t)k * CCH + tid;
    po[0]   = a0 * inv;
    po[256] = a1 * inv;
    po[512] = a2 * inv;
    po[768] = a3 * inv;
}

// ---------------- GEMM1 (512x1024 @ 1024x256) + BN + ReLU, 8 rois/block -----
__global__ void __launch_bounds__(256) k_gemm1(const float* __restrict__ W1,
                                               const float* __restrict__ b1,
                                               const float* __restrict__ gamma,
                                               const float* __restrict__ beta,
                                               const float* __restrict__ mm,
                                               const float* __restrict__ mv) {
    __shared__ float sp[8 * 1024];
    int r0  = blockIdx.x * 8;
    int tid = threadIdx.x;
    for (int i = tid; i < 8 * 1024; i += 256) sp[i] = g_pooled[(size_t)r0 * 1024 + i];
    __syncthreads();

    float acc[8];
    #pragma unroll
    for (int r = 0; r < 8; r++) acc[r] = 0.0f;

    for (int c = 0; c < 1024; c++) {
        float w = W1[c * 256 + tid];
        #pragma unroll
        for (int r = 0; r < 8; r++) acc[r] += sp[r * 1024 + c] * w;
    }

    float m  = mm[tid];
    float vr = rsqrtf(mv[tid] + 1e-3f);
    float ga = gamma[tid];
    float be = beta[tid];
    float bb = b1[tid];
    #pragma unroll
    for (int r = 0; r < 8; r++) {
        float h = (acc[r] + bb - m) * vr * ga + be;
        g_hdd[(size_t)(r0 + r) * 256 + tid] = fmaxf(h, 0.0f);
    }
}

// ---------------- GEMM2 (512x256 @ 256x84) + masked outputs -----------------
__global__ void __launch_bounds__(128) k_gemm2(const float* __restrict__ W2,
                                               const float* __restrict__ b2,
                                               float* __restrict__ out) {
    __shared__ float sh[256];
    int k   = blockIdx.x;
    int tid = threadIdx.x;
    for (int i = tid; i < 256; i += 128) sh[i] = g_hdd[(size_t)k * 256 + i];
    __syncthreads();

    float keepf = (float)g_keep[k];
    if (tid < OUTC) {
        float acc = b2[tid];
        for (int c = 0; c < 256; c++) acc += sh[c] * W2[c * OUTC + tid];
        if (tid < 4) {
            out[KSEL * 80 + k * 4 + tid] = (g_rois[k*4 + tid] + acc) * keepf;
        } else {
            out[(size_t)k * 80 + (tid - 4)] = acc * keepf;
        }
    }
    if (tid == 0) out[KSEL * 80 + KSEL * 4 + k] = keepf;
}

// ---------------- launch ----------------------------------------------------
extern "C" void kernel_launch(void* const* d_in, const int* in_sizes, int n_in,
                              void* d_out, int out_size) {
    const float* pred    = (const float*)d_in[0];
    const float* rois    = (const float*)d_in[1];
    const float* anchors = (const float*)d_in[2];
    const int*   assign  = (const int*)  d_in[3];
    const float* feats   = (const float*)d_in[4];
    const float* W1      = (const float*)d_in[5];
    const float* b1      = (const float*)d_in[6];
    const float* gamma   = (const float*)d_in[7];
    const float* beta    = (const float*)d_in[8];
    const float* mm      = (const float*)d_in[9];
    const float* mv      = (const float*)d_in[10];
    const float* W2      = (const float*)d_in[11];
    const float* b2      = (const float*)d_in[12];
    float* out = (float*)d_out;

    k_init<<<1, 32>>>();
    k_filter<<<(NTOT + 255) / 256, 256>>>(pred);
    k_select<<<1, 1024>>>(rois, anchors, assign);
    k_sup<<<(KSEL * 16 + 255) / 256, 256>>>();
    k_resolve<<<1, 32>>>();
    k_roialign<<<KSEL, 256>>>(feats);
    k_gemm1<<<KSEL / 8, 256>>>(W1, b1, gamma, beta, mm, mv);
    k_gemm2<<<KSEL, 128>>>(W2, b2, out);
}

// round 2
// speedup vs baseline: 1.0208x; 1.0208x over previous
#include <cuda_runtime.h>
#include <stdint.h>

#define NTOT  (8*32*32*9)   // 73728
#define KSEL  512
#define HF_   32
#define WF_   32
#define CCH   1024
#define FEAT  256
#define OUTC  84
#define SS_   14
#define NSAMP 196
#define DET_THRC 0.7f
#define NMS_IOUC 0.7f

// ---------------- device scratch (static globals; zero-initialized) ---------
__device__ uint64_t g_cand[NTOT];
__device__ int      g_cand_count;      // reset by k_select each run
__device__ int      g_valid[KSEL];
__device__ int      g_assign[KSEL];
__device__ float    g_rois[KSEL*4];
__device__ float    g_shifted[KSEL*4];
__device__ unsigned g_sup[KSEL*16];
__device__ unsigned g_supany[16];      // reset by k_resolve each run
__device__ int      g_keep[KSEL];
__device__ float    g_pooled[KSEL*CCH];
__device__ float    g_hdd[KSEL*FEAT];

// ---------------- filter: score > 0.7 -> 64-bit sortable key ----------------
// warp-aggregated atomic: 1 atomicAdd per warp instead of per candidate
__global__ void k_filter(const float* __restrict__ pred) {
    int i = blockIdx.x * blockDim.x + threadIdx.x;
    float s = (i < NTOT) ? pred[i] : 0.0f;
    bool c = (s > DET_THRC);
    unsigned m = __ballot_sync(0xffffffffu, c);
    int n = __popc(m);
    int base = 0;
    if ((threadIdx.x & 31) == 0 && n)
        base = atomicAdd(&g_cand_count, n);
    base = __shfl_sync(0xffffffffu, base, 0);
    if (c) {
        int r = __popc(m & ((1u << (threadIdx.x & 31)) - 1u));
        unsigned u = __float_as_uint(s); // s > 0 -> monotone as unsigned
        g_cand[base + r] = ((uint64_t)u << 32) | (unsigned)(0xFFFFFFFFu - (unsigned)i);
    }
}

// ---------------- single-block radix-select + bitonic sort top-512 ----------
__global__ void __launch_bounds__(1024) k_select(const float* __restrict__ rois,
                                                 const float* __restrict__ anchors,
                                                 const int*   __restrict__ assign) {
    __shared__ unsigned sh_hist[256];
    __shared__ unsigned sh_prefix;
    __shared__ int      sh_target;
    __shared__ int      sh_cnt;
    __shared__ uint64_t sh_keys[1024];
    int tid = threadIdx.x;
    int M = g_cand_count; if (M > NTOT) M = NTOT;
    __syncthreads();
    if (tid == 0) g_cand_count = 0;   // reset for next graph replay

    unsigned T = 1u; // collect everything valid if M <= KSEL
    if (M > KSEL) {
        if (tid == 0) { sh_prefix = 0u; sh_target = KSEL; }
        __syncthreads();
        for (int shift = 24; shift >= 0; shift -= 8) {
            if (tid < 256) sh_hist[tid] = 0u;
            __syncthreads();
            unsigned pfx = sh_prefix;
            for (int j = tid; j < M; j += 1024) {
                unsigned u = (unsigned)(g_cand[j] >> 32);
                bool match = (shift == 24) || ((u >> (shift + 8)) == (pfx >> (shift + 8)));
                if (match) atomicAdd(&sh_hist[(u >> shift) & 255], 1u);
            }
            __syncthreads();
            if (tid == 0) {
                int tgt = sh_target;
                int cum = 0; int chosen = 0;
                for (int d = 255; d >= 0; d--) {
                    cum += (int)sh_hist[d];
                    if (cum >= tgt) { chosen = d; sh_target = tgt - (cum - (int)sh_hist[d]); break; }
                }
                sh_prefix = pfx | ((unsigned)chosen << shift);
            }
            __syncthreads();
        }
        T = sh_prefix;
    }

    // collect keys with score-bits >= T
    if (tid == 0) sh_cnt = 0;
    __syncthreads();
    for (int j = tid; j < M; j += 1024) {
        uint64_t k = g_cand[j];
        unsigned u = (unsigned)(k >> 32);
        if (u >= T) {
            int p = atomicAdd(&sh_cnt, 1);
            if (p < 1024) sh_keys[p] = k;
        }
    }
    __syncthreads();
    int cnt = sh_cnt; if (cnt > 1024) cnt = 1024;
    if (tid >= cnt) sh_keys[tid] = 0ull;
    __syncthreads();

    // bitonic sort 1024 keys, descending (ties impossible: key embeds ~idx)
    for (int size = 2; size <= 1024; size <<= 1) {
        for (int stride = size >> 1; stride > 0; stride >>= 1) {
            int i = tid;
            int j = i ^ stride;
            if (j > i) {
                uint64_t a = sh_keys[i], b = sh_keys[j];
                bool descBlk = ((i & size) == 0);
                if (descBlk ? (a < b) : (a > b)) { sh_keys[i] = b; sh_keys[j] = a; }
            }
            __syncthreads();
        }
    }

    if (tid < KSEL) {
        uint64_t k = sh_keys[tid];
        unsigned u = (unsigned)(k >> 32);
        int idx = 0, v = 0;
        if (u != 0u) { idx = (int)(0xFFFFFFFFu - (unsigned)(k & 0xFFFFFFFFu)); v = 1; }
        g_valid[tid]   = v;
        int a = assign[idx];
        g_assign[tid]  = a;
        float fa = (float)a * 1024.0f;
        #pragma unroll
        for (int c = 0; c < 4; c++) g_rois[tid*4 + c] = rois[idx*4 + c];
        float cy = anchors[idx*4+0], cx = anchors[idx*4+1];
        float hh = anchors[idx*4+2], ww = anchors[idx*4+3];
        g_shifted[tid*4+0] = cy - hh*0.5f + fa;
        g_shifted[tid*4+1] = cx - ww*0.5f + fa;
        g_shifted[tid*4+2] = cy + hh*0.5f + fa;
        g_shifted[tid*4+3] = cx + ww*0.5f + fa;
    }
}

// ---------------- NMS suppression bitmask: thread = (box i, 32-j word) ------
// boxes staged in shared; division replaced by multiply-compare
__global__ void __launch_bounds__(256) k_sup() {
    __shared__ float4 sb[KSEL];
    int tid = threadIdx.x;
    const float4* gs = (const float4*)g_shifted;
    for (int i = tid; i < KSEL; i += 256) sb[i] = gs[i];
    __syncthreads();

    int gid = blockIdx.x * 256 + tid;
    int i = gid >> 4;
    int w = gid & 15;
    float4 bi = sb[i];
    float ai = (bi.z - bi.x) * (bi.w - bi.y);
    unsigned bits = 0u;
    #pragma unroll 8
    for (int b = 0; b < 32; b++) {
        int j = w*32 + b;
        if (j > i) {
            float4 bj = sb[j];
            float yA = fmaxf(bi.x, bj.x), xA = fmaxf(bi.y, bj.y);
            float yB = fminf(bi.z, bj.z), xB = fminf(bi.w, bj.w);
            float inter = fmaxf(yB - yA, 0.0f) * fmaxf(xB - xA, 0.0f);
            float aj = (bj.z - bj.x) * (bj.w - bj.y);
            // inter/(ai+aj-inter+eps) > thr  <=>  inter > thr*(ai+aj-inter+eps)
            if (inter > NMS_IOUC * (ai + aj - inter + 1e-8f)) bits |= (1u << b);
        }
    }
    g_sup[i*16 + w] = bits;
    if (bits) atomicOr(&g_supany[i >> 5], 1u << (i & 31));
}

// ---------------- sequential greedy resolve, 1 warp, skip empty rows --------
__global__ void k_resolve() {
    int lane = threadIdx.x;
    unsigned word = 0u;
    if (lane < 16) {
        #pragma unroll
        for (int b = 0; b < 32; b++)
            if (g_valid[lane*32 + b]) word |= (1u << b);
    }
    for (int w = 0; w < 16; w++) {
        unsigned anyw = g_supany[w];   // uniform across lanes
        if (!anyw) continue;
        for (int b = 0; b < 32; b++) {
            if (!((anyw >> b) & 1u)) continue;
            int i = w*32 + b;
            unsigned wi = __shfl_sync(0xffffffffu, word, w);
            if ((wi >> b) & 1u) {
                if (lane < 16) word &= ~g_sup[i*16 + lane];
            }
        }
    }
    if (lane < 16) {
        #pragma unroll
        for (int b = 0; b < 32; b++)
            g_keep[lane*32 + b] = (int)((word >> b) & 1u);
        g_supany[lane] = 0u;           // reset for next graph replay
    }
}

// ---------------- ROI align via per-pixel weight map (1 block / roi) --------
__global__ void __launch_bounds__(256) k_roialign(const float* __restrict__ feats) {
    __shared__ float wmap[1024];
    __shared__ int   plist[512];
    __shared__ float wlist[512];
    __shared__ int   cnt;
    int k   = blockIdx.x;
    int tid = threadIdx.x;
    for (int i = tid; i < 1024; i += 256) wmap[i] = 0.0f;
    if (tid == 0) cnt = 0;
    __syncthreads();

    const float sc = 32.0f / 1024.0f;
    float ry1 = g_rois[k*4+0] * sc, rx1 = g_rois[k*4+1] * sc;
    float ry2 = g_rois[k*4+2] * sc, rx2 = g_rois[k*4+3] * sc;

    if (tid < NSAMP) {
        int sy = tid / SS_, sx = tid % SS_;
        float fy = ((float)sy + 0.5f) / (float)SS_;
        float fx = ((float)sx + 0.5f) / (float)SS_;
        float yy = ry1 + fy * (ry2 - ry1) - 0.5f;
        float xx = rx1 + fx * (rx2 - rx1) - 0.5f;
        float yc = fminf(fmaxf(yy, 0.0f), 31.0f);
        float xc = fminf(fmaxf(xx, 0.0f), 31.0f);
        float y0 = floorf(yc), x0 = floorf(xc);
        float wy = yc - y0,  wx = xc - x0;
        int y0i = (int)y0, x0i = (int)x0;
        int y1i = min(y0i + 1, 31), x1i = min(x0i + 1, 31);
        atomicAdd(&wmap[y0i*32 + x0i], (1.0f - wy) * (1.0f - wx));
        atomicAdd(&wmap[y0i*32 + x1i], (1.0f - wy) * wx);
        atomicAdd(&wmap[y1i*32 + x0i], wy * (1.0f - wx));
        atomicAdd(&wmap[y1i*32 + x1i], wy * wx);
    }
    __syncthreads();

    for (int p = tid; p < 1024; p += 256) {
        float w = wmap[p];
        if (w != 0.0f) {
            int pos = atomicAdd(&cnt, 1);
            plist[pos] = p; wlist[pos] = w;
        }
    }
    __syncthreads();

    int n = cnt;
    const float* fb = feats + (size_t)g_assign[k] * (HF_ * WF_ * CCH);
    float a0 = 0.f, a1 = 0.f, a2 = 0.f, a3 = 0.f;
    #pragma unroll 2
    for (int e = 0; e < n; e++) {
        int   p = plist[e];
        float w = wlist[e];
        const float* row = fb + (size_t)p * CCH + tid;
        a0 += w * row[0];
        a1 += w * row[256];
        a2 += w * row[512];
        a3 += w * row[768];
    }
    const float inv = 1.0f / 196.0f;
    float* po = g_pooled + (size_t)k * CCH + tid;
    po[0]   = a0 * inv;
    po[256] = a1 * inv;
    po[512] = a2 * inv;
    po[768] = a3 * inv;
}

// ------- GEMM1 (512x1024 @ 1024x256) + BN + ReLU, 8 rois x 128 cols / block -
__global__ void __launch_bounds__(128) k_gemm1(const float* __restrict__ W1,
                                               const float* __restrict__ b1,
                                               const float* __restrict__ gamma,
                                               const float* __restrict__ beta,
                                               const float* __restrict__ mm,
                                               const float* __restrict__ mv) {
    __shared__ float sp[8 * 1024];
    int r0  = (blockIdx.x >> 1) * 8;
    int col = ((blockIdx.x & 1) << 7) | threadIdx.x;

    const float4* src = (const float4*)(g_pooled + (size_t)r0 * 1024);
    float4* dst = (float4*)sp;
    for (int i = threadIdx.x; i < 2048; i += 128) dst[i] = src[i];
    __syncthreads();

    float acc[8];
    #pragma unroll
    for (int r = 0; r < 8; r++) acc[r] = 0.0f;

    for (int c = 0; c < 1024; c += 4) {
        float w0 = W1[(c+0) * 256 + col];
        float w1 = W1[(c+1) * 256 + col];
        float w2 = W1[(c+2) * 256 + col];
        float w3 = W1[(c+3) * 256 + col];
        #pragma unroll
        for (int r = 0; r < 8; r++) {
            float4 p = *(const float4*)&sp[r * 1024 + c];
            acc[r] += p.x * w0 + p.y * w1 + p.z * w2 + p.w * w3;
        }
    }

    float m  = mm[col];
    float vr = rsqrtf(mv[col] + 1e-3f);
    float ga = gamma[col];
    float be = beta[col];
    float bb = b1[col];
    #pragma unroll
    for (int r = 0; r < 8; r++) {
        float h = (acc[r] + bb - m) * vr * ga + be;
        g_hdd[(size_t)(r0 + r) * 256 + col] = fmaxf(h, 0.0f);
    }
}

// ---------------- GEMM2 (512x256 @ 256x84) + masked outputs, 4 rois/block ---
__global__ void __launch_bounds__(128) k_gemm2(const float* __restrict__ W2,
                                               const float* __restrict__ b2,
                                               float* __restrict__ out) {
    __shared__ float sh[4 * 256];
    int r0  = blockIdx.x * 4;
    int tid = threadIdx.x;
    for (int i = tid; i < 1024; i += 128) sh[i] = g_hdd[(size_t)r0 * 256 + i];
    __syncthreads();

    if (tid < OUTC) {
        float acc[4];
        float bb = b2[tid];
        #pragma unroll
        for (int r = 0; r < 4; r++) acc[r] = bb;
        for (int c = 0; c < 256; c++) {
            float w = W2[c * OUTC + tid];
            #pragma unroll
            for (int r = 0; r < 4; r++) acc[r] += sh[r * 256 + c] * w;
        }
        #pragma unroll
        for (int r = 0; r < 4; r++) {
            int k = r0 + r;
            float keepf = (float)g_keep[k];
            if (tid < 4) out[KSEL*80 + k*4 + tid] = (g_rois[k*4 + tid] + acc[r]) * keepf;
            else         out[(size_t)k*80 + (tid - 4)] = acc[r] * keepf;
        }
    }
    if (tid >= 96 && tid < 100) {
        int k = r0 + (tid - 96);
        out[KSEL*80 + KSEL*4 + k] = (float)g_keep[k];
    }
}

// ---------------- launch ----------------------------------------------------
extern "C" void kernel_launch(void* const* d_in, const int* in_sizes, int n_in,
                              void* d_out, int out_size) {
    const float* pred    = (const float*)d_in[0];
    const float* rois    = (const float*)d_in[1];
    const float* anchors = (const float*)d_in[2];
    const int*   assign  = (const int*)  d_in[3];
    const float* feats   = (const float*)d_in[4];
    const float* W1      = (const float*)d_in[5];
    const float* b1      = (const float*)d_in[6];
    const float* gamma   = (const float*)d_in[7];
    const float* beta    = (const float*)d_in[8];
    const float* mm      = (const float*)d_in[9];
    const float* mv      = (const float*)d_in[10];
    const float* W2      = (const float*)d_in[11];
    const float* b2      = (const float*)d_in[12];
    float* out = (float*)d_out;

    k_filter<<<(NTOT + 255) / 256, 256>>>(pred);
    k_select<<<1, 1024>>>(rois, anchors, assign);
    k_sup<<<KSEL * 16 / 256, 256>>>();
    k_resolve<<<1, 32>>>();
    k_roialign<<<KSEL, 256>>>(feats);
    k_gemm1<<<128, 128>>>(W1, b1, gamma, beta, mm, mv);
    k_gemm2<<<KSEL / 4, 128>>>(W2, b2, out);
}

// round 3
// speedup vs baseline: 1.1876x; 1.1634x over previous
#include <cuda_runtime.h>
#include <stdint.h>

#define NTOT  (8*32*32*9)   // 73728
#define KSEL  512
#define HF_   32
#define WF_   32
#define CCH   1024
#define FEAT  256
#define OUTC  84
#define SS_   14
#define NSAMP 196
#define DET_THRC 0.7f
#define NMS_IOUC 0.7f
#define NBINS 4096

typedef unsigned long long ull;

// ---------------- device scratch (static globals; zero-initialized) ---------
__device__ uint64_t g_cand[NTOT];
__device__ int      g_cand_count;                 // reset by k_select
__device__ __align__(16) int g_hist[NBINS];       // reset by k_select
__device__ int      g_valid[KSEL];
__device__ int      g_assign[KSEL];
__device__ float    g_rois[KSEL*4];
__device__ float    g_shifted[KSEL*4];
__device__ unsigned g_sup[KSEL*16];
__device__ unsigned g_supany[16];                 // reset by k_resolve
__device__ int      g_keep[KSEL];
__device__ float    g_poolT[KSEL*CCH];            // [group=k/8][c][k%8]
__device__ float    g_hdd[KSEL*FEAT];

// ---------------- filter: score > 0.7 -> key + 4096-bin histogram -----------
__global__ void k_filter(const float* __restrict__ pred) {
    int i = blockIdx.x * blockDim.x + threadIdx.x;
    float s = (i < NTOT) ? pred[i] : 0.0f;
    bool c = (s > DET_THRC);
    unsigned m = __ballot_sync(0xffffffffu, c);
    int n = __popc(m);
    int base = 0;
    if ((threadIdx.x & 31) == 0 && n)
        base = atomicAdd(&g_cand_count, n);
    base = __shfl_sync(0xffffffffu, base, 0);
    if (c) {
        int r = __popc(m & ((1u << (threadIdx.x & 31)) - 1u));
        unsigned u = __float_as_uint(s); // s > 0 -> monotone as unsigned
        g_cand[base + r] = ((uint64_t)u << 32) | (unsigned)(0xFFFFFFFFu - (unsigned)i);
        atomicAdd(&g_hist[u >> 19], 1);
    }
}

// ------- single-block: histogram cutoff + 1-pass collect + hybrid bitonic ---
__global__ void __launch_bounds__(1024) k_select(const float* __restrict__ rois,
                                                 const float* __restrict__ anchors,
                                                 const int*   __restrict__ assign) {
    __shared__ int      sh_hist[NBINS];
    __shared__ int      sh_chunk[1024];
    __shared__ int      sh_warp[32];
    __shared__ unsigned sh_T;
    __shared__ int      sh_cnt;
    __shared__ uint64_t sh_keys[1024];
    int tid = threadIdx.x;
    int lane = tid & 31, wid = tid >> 5;

    int M = g_cand_count; if (M > NTOT) M = NTOT;
    __syncthreads();
    if (tid == 0) { g_cand_count = 0; sh_cnt = 0; }

    // load + reset histogram; per-thread chunk = 4 bins
    int4 h = ((const int4*)g_hist)[tid];
    ((int4*)g_hist)[tid] = make_int4(0, 0, 0, 0);
    sh_hist[tid*4+0] = h.x; sh_hist[tid*4+1] = h.y;
    sh_hist[tid*4+2] = h.z; sh_hist[tid*4+3] = h.w;
    int csum = h.x + h.y + h.z + h.w;
    sh_chunk[tid] = csum;
    int ws = csum;
    #pragma unroll
    for (int off = 16; off > 0; off >>= 1) ws += __shfl_down_sync(0xffffffffu, ws, off);
    if (lane == 0) sh_warp[wid] = ws;
    __syncthreads();

    if (tid == 0) {
        unsigned T = 1u;
        int cum = 0; int w;
        bool found = false;
        for (w = 31; w >= 0; w--) {
            if (cum + sh_warp[w] >= KSEL) { found = true; break; }
            cum += sh_warp[w];
        }
        if (found) {
            int c;
            for (c = 31; c >= 0; c--) {
                int t = sh_chunk[w*32 + c];
                if (cum + t >= KSEL) break;
                cum += t;
            }
            int base = (w*32 + c) * 4;
            int b;
            for (b = 3; b >= 0; b--) {
                int t = sh_hist[base + b];
                if (cum + t >= KSEL) break;
                cum += t;
            }
            T = (unsigned)(base + b) << 19;
        }
        sh_T = T;
    }
    __syncthreads();
    unsigned T = sh_T;

    // single collection pass
    for (int j = tid; j < M; j += 1024) {
        uint64_t k = g_cand[j];
        if ((unsigned)(k >> 32) >= T) {
            int p = atomicAdd(&sh_cnt, 1);
            if (p < 1024) sh_keys[p] = k;
        }
    }
    __syncthreads();
    int cnt = sh_cnt; if (cnt > 1024) cnt = 1024;
    if (tid >= cnt) sh_keys[tid] = 0ull;
    __syncthreads();

    // hybrid bitonic sort (descending): strides<=16 via shfl, >=32 via shared
    uint64_t v = sh_keys[tid];
    #pragma unroll
    for (int size = 2; size <= 32; size <<= 1) {
        #pragma unroll
        for (int stride = size >> 1; stride >= 1; stride >>= 1) {
            uint64_t o = __shfl_xor_sync(0xffffffffu, v, stride);
            bool lower = (tid & stride) == 0;
            bool desc  = (tid & size) == 0;
            uint64_t mx = v > o ? v : o, mn = v > o ? o : v;
            v = (desc == lower) ? mx : mn;
        }
    }
    sh_keys[tid] = v;
    __syncthreads();
    for (int size = 64; size <= 1024; size <<= 1) {
        for (int stride = size >> 1; stride >= 32; stride >>= 1) {
            int j = tid ^ stride;
            if (j > tid) {
                uint64_t a = sh_keys[tid], b = sh_keys[j];
                bool desc = (tid & size) == 0;
                if (desc ? (a < b) : (a > b)) { sh_keys[tid] = b; sh_keys[j] = a; }
            }
            __syncthreads();
        }
        v = sh_keys[tid];
        #pragma unroll
        for (int stride = 16; stride >= 1; stride >>= 1) {
            uint64_t o = __shfl_xor_sync(0xffffffffu, v, stride);
            bool lower = (tid & stride) == 0;
            bool desc  = (tid & size) == 0;
            uint64_t mx = v > o ? v : o, mn = v > o ? o : v;
            v = (desc == lower) ? mx : mn;
        }
        sh_keys[tid] = v;
        __syncthreads();
    }

    if (tid < KSEL) {
        uint64_t k = sh_keys[tid];
        unsigned u = (unsigned)(k >> 32);
        int idx = 0, vv = 0;
        if (u != 0u) { idx = (int)(0xFFFFFFFFu - (unsigned)(k & 0xFFFFFFFFu)); vv = 1; }
        g_valid[tid] = vv;
        int a = assign[idx];
        g_assign[tid] = a;
        float fa = (float)a * 1024.0f;
        #pragma unroll
        for (int c = 0; c < 4; c++) g_rois[tid*4 + c] = rois[idx*4 + c];
        float cy = anchors[idx*4+0], cx = anchors[idx*4+1];
        float hh = anchors[idx*4+2], ww = anchors[idx*4+3];
        g_shifted[tid*4+0] = cy - hh*0.5f + fa;
        g_shifted[tid*4+1] = cx - ww*0.5f + fa;
        g_shifted[tid*4+2] = cy + hh*0.5f + fa;
        g_shifted[tid*4+3] = cx + ww*0.5f + fa;
    }
}

// ---------------- NMS suppression bitmask (boxes staged in shared) ----------
__global__ void __launch_bounds__(256) k_sup() {
    __shared__ float4 sb[KSEL];
    int tid = threadIdx.x;
    const float4* gs = (const float4*)g_shifted;
    for (int i = tid; i < KSEL; i += 256) sb[i] = gs[i];
    __syncthreads();

    int gid = blockIdx.x * 256 + tid;
    int i = gid >> 4;
    int w = gid & 15;
    float4 bi = sb[i];
    float ai = (bi.z - bi.x) * (bi.w - bi.y);
    unsigned bits = 0u;
    #pragma unroll 8
    for (int b = 0; b < 32; b++) {
        int j = w*32 + b;
        if (j > i) {
            float4 bj = sb[j];
            float yA = fmaxf(bi.x, bj.x), xA = fmaxf(bi.y, bj.y);
            float yB = fminf(bi.z, bj.z), xB = fminf(bi.w, bj.w);
            float inter = fmaxf(yB - yA, 0.0f) * fmaxf(xB - xA, 0.0f);
            float aj = (bj.z - bj.x) * (bj.w - bj.y);
            if (inter > NMS_IOUC * (ai + aj - inter + 1e-8f)) bits |= (1u << b);
        }
    }
    g_sup[i*16 + w] = bits;
    if (bits) atomicOr(&g_supany[i >> 5], 1u << (i & 31));
}

// ---------------- greedy resolve: stage everything in shared first ----------
__global__ void __launch_bounds__(512) k_resolve() {
    __shared__ unsigned ssup[KSEL*16];
    __shared__ unsigned sany[16];
    __shared__ unsigned sword[16];
    int tid = threadIdx.x;
    #pragma unroll
    for (int i = tid; i < KSEL*16; i += 512) ssup[i] = g_sup[i];
    int v = g_valid[tid];
    unsigned bm = __ballot_sync(0xffffffffu, v != 0);
    if ((tid & 31) == 0) sword[tid >> 5] = bm;
    if (tid < 16) { sany[tid] = g_supany[tid]; g_supany[tid] = 0u; }
    __syncthreads();

    if (tid < 32) {
        int lane = tid;
        unsigned word = (lane < 16) ? sword[lane] : 0u;
        for (int w = 0; w < 16; w++) {
            unsigned anyw = sany[w];
            if (!anyw) continue;
            for (int b = 0; b < 32; b++) {
                if (!((anyw >> b) & 1u)) continue;
                int i = w*32 + b;
                unsigned wi = __shfl_sync(0xffffffffu, word, w);
                if ((wi >> b) & 1u) {
                    if (lane < 16) word &= ~ssup[i*16 + lane];
                }
            }
        }
        if (lane < 16) sword[lane] = word;
    }
    __syncthreads();
    g_keep[tid] = (int)((sword[tid >> 5] >> (tid & 31)) & 1u);
}

// ------- ROI align via pixel weight map; writes transposed pooled -----------
__global__ void __launch_bounds__(256) k_roialign(const float* __restrict__ feats) {
    __shared__ float wmap[1024];
    __shared__ int   plist[512];
    __shared__ float wlist[512];
    __shared__ int   cnt;
    int k   = blockIdx.x;
    int tid = threadIdx.x;
    for (int i = tid; i < 1024; i += 256) wmap[i] = 0.0f;
    if (tid == 0) cnt = 0;
    __syncthreads();

    const float sc = 32.0f / 1024.0f;
    float ry1 = g_rois[k*4+0] * sc, rx1 = g_rois[k*4+1] * sc;
    float ry2 = g_rois[k*4+2] * sc, rx2 = g_rois[k*4+3] * sc;

    if (tid < NSAMP) {
        int sy = tid / SS_, sx = tid % SS_;
        float fy = ((float)sy + 0.5f) / (float)SS_;
        float fx = ((float)sx + 0.5f) / (float)SS_;
        float yy = ry1 + fy * (ry2 - ry1) - 0.5f;
        float xx = rx1 + fx * (rx2 - rx1) - 0.5f;
        float yc = fminf(fmaxf(yy, 0.0f), 31.0f);
        float xc = fminf(fmaxf(xx, 0.0f), 31.0f);
        float y0 = floorf(yc), x0 = floorf(xc);
        float wy = yc - y0,  wx = xc - x0;
        int y0i = (int)y0, x0i = (int)x0;
        int y1i = min(y0i + 1, 31), x1i = min(x0i + 1, 31);
        atomicAdd(&wmap[y0i*32 + x0i], (1.0f - wy) * (1.0f - wx));
        atomicAdd(&wmap[y0i*32 + x1i], (1.0f - wy) * wx);
        atomicAdd(&wmap[y1i*32 + x0i], wy * (1.0f - wx));
        atomicAdd(&wmap[y1i*32 + x1i], wy * wx);
    }
    __syncthreads();

    for (int p = tid; p < 1024; p += 256) {
        float w = wmap[p];
        if (w != 0.0f) {
            int pos = atomicAdd(&cnt, 1);
            plist[pos] = p; wlist[pos] = w;
        }
    }
    __syncthreads();

    int n = cnt;
    const float* fb = feats + (size_t)g_assign[k] * (HF_ * WF_ * CCH);
    float a0 = 0.f, a1 = 0.f, a2 = 0.f, a3 = 0.f;
    #pragma unroll 2
    for (int e = 0; e < n; e++) {
        int   p = plist[e];
        float w = wlist[e];
        const float* row = fb + (size_t)p * CCH + tid;
        a0 += w * row[0];
        a1 += w * row[256];
        a2 += w * row[512];
        a3 += w * row[768];
    }
    const float inv = 1.0f / 196.0f;
    float* po = g_poolT + (size_t)(k >> 3) * 8192 + (k & 7);
    po[(size_t)(tid      ) * 8] = a0 * inv;
    po[(size_t)(tid + 256) * 8] = a1 * inv;
    po[(size_t)(tid + 512) * 8] = a2 * inv;
    po[(size_t)(tid + 768) * 8] = a3 * inv;
}

// ------- GEMM1 via packed fma.rn.f32x2: 8 rois x 128 cols per block ---------
__global__ void __launch_bounds__(128) k_gemm1(const float* __restrict__ W1,
                                               const float* __restrict__ b1,
                                               const float* __restrict__ gamma,
                                               const float* __restrict__ beta,
                                               const float* __restrict__ mm,
                                               const float* __restrict__ mv) {
    __shared__ float sp[8192];           // [c][8 rois]
    int g   = blockIdx.x >> 1;
    int r0  = g * 8;
    int col = ((blockIdx.x & 1) << 7) | threadIdx.x;

    const float4* src = (const float4*)(g_poolT + (size_t)g * 8192);
    float4* dst = (float4*)sp;
    for (int i = threadIdx.x; i < 2048; i += 128) dst[i] = src[i];
    __syncthreads();

    ull acc0 = 0ull, acc1 = 0ull, acc2 = 0ull, acc3 = 0ull;
    const ull* spu = (const ull*)sp;
    #pragma unroll 4
    for (int c = 0; c < 1024; c++) {
        float w = W1[c * 256 + col];
        ull w2;
        asm("mov.b64 %0, {%1, %1};" : "=l"(w2) : "r"(__float_as_uint(w)));
        ull p0 = spu[c*4 + 0], p1 = spu[c*4 + 1];
        ull p2 = spu[c*4 + 2], p3 = spu[c*4 + 3];
        asm("fma.rn.f32x2 %0, %1, %2, %0;" : "+l"(acc0) : "l"(p0), "l"(w2));
        asm("fma.rn.f32x2 %0, %1, %2, %0;" : "+l"(acc1) : "l"(p1), "l"(w2));
        asm("fma.rn.f32x2 %0, %1, %2, %0;" : "+l"(acc2) : "l"(p2), "l"(w2));
        asm("fma.rn.f32x2 %0, %1, %2, %0;" : "+l"(acc3) : "l"(p3), "l"(w2));
    }

    float af[8];
    {
        unsigned lo, hi;
        asm("mov.b64 {%0, %1}, %2;" : "=r"(lo), "=r"(hi) : "l"(acc0));
        af[0] = __uint_as_float(lo); af[1] = __uint_as_float(hi);
        asm("mov.b64 {%0, %1}, %2;" : "=r"(lo), "=r"(hi) : "l"(acc1));
        af[2] = __uint_as_float(lo); af[3] = __uint_as_float(hi);
        asm("mov.b64 {%0, %1}, %2;" : "=r"(lo), "=r"(hi) : "l"(acc2));
        af[4] = __uint_as_float(lo); af[5] = __uint_as_float(hi);
        asm("mov.b64 {%0, %1}, %2;" : "=r"(lo), "=r"(hi) : "l"(acc3));
        af[6] = __uint_as_float(lo); af[7] = __uint_as_float(hi);
    }

    float m  = mm[col];
    float vr = rsqrtf(mv[col] + 1e-3f);
    float ga = gamma[col];
    float be = beta[col];
    float bb = b1[col];
    #pragma unroll
    for (int r = 0; r < 8; r++) {
        float hv = (af[r] + bb - m) * vr * ga + be;
        g_hdd[(size_t)(r0 + r) * 256 + col] = fmaxf(hv, 0.0f);
    }
}

// ---------------- GEMM2 (512x256 @ 256x84) + masked outputs, 4 rois/block ---
__global__ void __launch_bounds__(128) k_gemm2(const float* __restrict__ W2,
                                               const float* __restrict__ b2,
                                               float* __restrict__ out) {
    __shared__ float sh[4 * 256];
    int r0  = blockIdx.x * 4;
    int tid = threadIdx.x;
    for (int i = tid; i < 1024; i += 128) sh[i] = g_hdd[(size_t)r0 * 256 + i];
    __syncthreads();

    if (tid < OUTC) {
        float acc[4];
        float bb = b2[tid];
        #pragma unroll
        for (int r = 0; r < 4; r++) acc[r] = bb;
        for (int c = 0; c < 256; c++) {
            float w = W2[c * OUTC + tid];
            #pragma unroll
            for (int r = 0; r < 4; r++) acc[r] += sh[r * 256 + c] * w;
        }
        #pragma unroll
        for (int r = 0; r < 4; r++) {
            int k = r0 + r;
            float keepf = (float)g_keep[k];
            if (tid < 4) out[KSEL*80 + k*4 + tid] = (g_rois[k*4 + tid] + acc[r]) * keepf;
            else         out[(size_t)k*80 + (tid - 4)] = acc[r] * keepf;
        }
    }
    if (tid >= 96 && tid < 100) {
        int k = r0 + (tid - 96);
        out[KSEL*80 + KSEL*4 + k] = (float)g_keep[k];
    }
}

// ---------------- launch ----------------------------------------------------
extern "C" void kernel_launch(void* const* d_in, const int* in_sizes, int n_in,
                              void* d_out, int out_size) {
    const float* pred    = (const float*)d_in[0];
    const float* rois    = (const float*)d_in[1];
    const float* anchors = (const float*)d_in[2];
    const int*   assign  = (const int*)  d_in[3];
    const float* feats   = (const float*)d_in[4];
    const float* W1      = (const float*)d_in[5];
    const float* b1      = (const float*)d_in[6];
    const float* gamma   = (const float*)d_in[7];
    const float* beta    = (const float*)d_in[8];
    const float* mm      = (const float*)d_in[9];
    const float* mv      = (const float*)d_in[10];
    const float* W2      = (const float*)d_in[11];
    const float* b2      = (const float*)d_in[12];
    float* out = (float*)d_out;

    k_filter<<<(NTOT + 255) / 256, 256>>>(pred);
    k_select<<<1, 1024>>>(rois, anchors, assign);
    k_sup<<<KSEL * 16 / 256, 256>>>();
    k_resolve<<<1, 512>>>();
    k_roialign<<<KSEL, 256>>>(feats);
    k_gemm1<<<128, 128>>>(W1, b1, gamma, beta, mm, mv);
    k_gemm2<<<KSEL / 4, 128>>>(W2, b2, out);
}